// round 2
// baseline (speedup 1.0000x reference)
#include <cuda_runtime.h>
#include <cstdint>

// ---------------------------------------------------------------------------
// Problem constants
// ---------------------------------------------------------------------------
constexpr int BATCH = 2;
constexpr int NPTS  = 4096;
constexpr int KNN_K = 16;
constexpr int C     = 128;
constexpr int CIN   = 64;
constexpr int GRP   = 8;          // groups
constexpr int LBIG  = NPTS * KNN_K;   // 65536
constexpr float GN_EPS = 1e-5f;
constexpr float GN_INVCOUNT = 1.0f / (16.0f * NPTS * KNN_K); // per (b,group) element count

// ---------------------------------------------------------------------------
// Scratch (device globals; allocation-free per harness rules)
// ---------------------------------------------------------------------------
__device__ float g_feat1T[BATCH * NPTS * CIN];
__device__ float g_feat2T[BATCH * NPTS * CIN];
__device__ float g_f1T[BATCH * NPTS * C];
__device__ float g_f2T[BATCH * NPTS * C];
__device__ float g_g1T[BATCH * NPTS * C];
__device__ float g_g2T[BATCH * NPTS * C];
__device__ float g_f1nT[BATCH * NPTS * C];
__device__ float g_f2nT[BATCH * NPTS * C];
__device__ float g_cross[BATCH * NPTS * C];
__device__ int   g_idx12[BATCH * NPTS * KNN_K];
__device__ int   g_idx21[BATCH * NPTS * KNN_K];
__device__ float g_XA[(size_t)BATCH * LBIG * C];   // 64 MB
__device__ float g_XB[(size_t)BATCH * LBIG * C];   // 64 MB
__device__ float g_stats[8 * BATCH * GRP * 2];     // 8 stages
__device__ float g_sb[8 * BATCH * C * 2];          // per-stage (scale,bias)

// ---------------------------------------------------------------------------
// Zero the stats buffers (must run first every launch; determinism)
// ---------------------------------------------------------------------------
__global__ void zero_stats_kernel() {
    int i = threadIdx.x;                // 256 threads, exactly 8*2*8*2 floats
    g_stats[i] = 0.0f;
}

// ---------------------------------------------------------------------------
// Transpose [B][CIN][N] -> [B][N][CIN]
// ---------------------------------------------------------------------------
__global__ void transpose64_kernel(const float* __restrict__ in, float* __restrict__ out) {
    int i = blockIdx.x * 256 + threadIdx.x;       // over B*N*CIN = 524288
    int c = i & 63;
    int n = (i >> 6) & (NPTS - 1);
    int b = i >> 18;
    out[i] = __ldg(&in[((size_t)b * CIN + c) * NPTS + n]);
}

// ---------------------------------------------------------------------------
// Brute-force KNN: one block per query point. d2 = |q|^2 + |p|^2 - 2 q.p,
// 16 rounds of packed (dist,idx) argmin with tie-break to lower index.
// ---------------------------------------------------------------------------
__global__ void knn_kernel(const float* __restrict__ xyzQ,
                           const float* __restrict__ xyzD,
                           int* __restrict__ out) {
    __shared__ float d2[NPTS];
    __shared__ unsigned long long red[256];
    int n = blockIdx.x, b = blockIdx.y, tid = threadIdx.x;
    const float* Q = xyzQ + (size_t)b * 3 * NPTS;
    const float* D = xyzD + (size_t)b * 3 * NPTS;
    float qx = Q[n], qy = Q[NPTS + n], qz = Q[2 * NPTS + n];
    float s1 = qx * qx + qy * qy + qz * qz;
    for (int j = tid; j < NPTS; j += 256) {
        float px = D[j], py = D[NPTS + j], pz = D[2 * NPTS + j];
        float dot = qx * px + qy * py + qz * pz;
        float s2 = px * px + py * py + pz * pz;
        d2[j] = s1 + s2 - 2.0f * dot;
    }
    __syncthreads();
    for (int r = 0; r < KNN_K; r++) {
        unsigned long long best = ~0ull;
        for (int j = tid; j < NPTS; j += 256) {
            unsigned u = __float_as_uint(d2[j]);
            u = (u & 0x80000000u) ? ~u : (u | 0x80000000u);
            unsigned long long key = ((unsigned long long)u << 32) | (unsigned)j;
            best = min(best, key);
        }
        red[tid] = best;
        __syncthreads();
        for (int off = 128; off > 0; off >>= 1) {
            if (tid < off) red[tid] = min(red[tid], red[tid + off]);
            __syncthreads();
        }
        if (tid == 0) {
            int j = (int)(red[0] & 0xffffffffu);
            out[((size_t)b * NPTS + n) * KNN_K + r] = j;
            d2[j] = __int_as_float(0x7f800000);   // +inf
        }
        __syncthreads();
    }
}

// ---------------------------------------------------------------------------
// Assemble:  X0[b][n*16+k][c] = p2T[b][idx][c] + p1T[b][n][c] + pos(dir) ,
// plus per-(b,group) sum/sumsq stats via one block-level reduction + atomics.
// Block = 128 threads (c), 32 points per block.
// ---------------------------------------------------------------------------
__global__ void assemble_kernel(const float* __restrict__ xyz1,
                                const float* __restrict__ xyz2,
                                const float* __restrict__ p1T,
                                const float* __restrict__ p2T,
                                const int* __restrict__ idx,
                                const float* __restrict__ posw,
                                const float* __restrict__ posb,
                                float* __restrict__ X0,
                                float* __restrict__ stats) {
    __shared__ float sdx[16], sdy[16], sdz[16];
    __shared__ int sj[16];
    __shared__ float rs[128], rq[128];
    int c = threadIdx.x;
    int b = blockIdx.y;
    int nbase = blockIdx.x * 32;
    float pwx = posw[c * 3 + 0], pwy = posw[c * 3 + 1], pwz = posw[c * 3 + 2];
    float pb = posb[c];
    float lsum = 0.f, lsq = 0.f;
    const float* x1 = xyz1 + (size_t)b * 3 * NPTS;
    const float* x2 = xyz2 + (size_t)b * 3 * NPTS;
    for (int np = 0; np < 32; np++) {
        int n = nbase + np;
        __syncthreads();
        if (c < 16) {
            int j = idx[((size_t)b * NPTS + n) * KNN_K + c];
            sj[c] = j;
            sdx[c] = x2[j]            - x1[n];
            sdy[c] = x2[NPTS + j]     - x1[NPTS + n];
            sdz[c] = x2[2 * NPTS + j] - x1[2 * NPTS + n];
        }
        __syncthreads();
        float p1v = p1T[((size_t)b * NPTS + n) * C + c];
        #pragma unroll
        for (int k = 0; k < KNN_K; k++) {
            float v = p2T[((size_t)b * NPTS + sj[k]) * C + c] + p1v +
                      pwx * sdx[k] + pwy * sdy[k] + pwz * sdz[k] + pb;
            X0[(((size_t)b * NPTS + n) * KNN_K + k) * C + c] = v;
            lsum += v; lsq += v * v;
        }
    }
    rs[c] = lsum; rq[c] = lsq;
    __syncthreads();
    #pragma unroll
    for (int off = 8; off > 0; off >>= 1) {
        if ((c & 15) < off) { rs[c] += rs[c + off]; rq[c] += rq[c + off]; }
        __syncthreads();
    }
    if ((c & 15) == 0) {
        int g = c >> 4;
        atomicAdd(&stats[(b * GRP + g) * 2 + 0], rs[c]);
        atomicAdd(&stats[(b * GRP + g) * 2 + 1], rq[c]);
    }
}

// ---------------------------------------------------------------------------
// Finalize GN stats -> per-channel (scale, bias).
// scale = gamma * rsqrt(var+eps), bias = beta - mean*scale.
// ---------------------------------------------------------------------------
__global__ void finalize_kernel(const float* __restrict__ stats,
                                const float* __restrict__ gamma,
                                const float* __restrict__ beta,
                                float* __restrict__ sb,
                                float invcount) {
    int i = threadIdx.x;              // 256 = B*C
    int b = i >> 7, c = i & 127, g = c >> 4;
    float sum = stats[(b * GRP + g) * 2 + 0];
    float sq  = stats[(b * GRP + g) * 2 + 1];
    float mean = sum * invcount;
    float var  = sq * invcount - mean * mean;
    float s = gamma[c] * rsqrtf(var + GN_EPS);
    sb[i * 2 + 0] = s;
    sb[i * 2 + 1] = beta[c] - mean * s;
}

// ---------------------------------------------------------------------------
// SGEMM:  out[o][l] = sum_c W[o][c] * f(X[l][c]) + bias[o]
//   f = identity, or lrelu(x*scale_c + bias_c) when sb != null (fused GN+act)
//   outLC: [B][L][128] (l-major),  outCL: [B][128][L] (o-major) — either nullable
//   stats: per-(b,group) sum/sumsq of the (bias-added) outputs, nullable.
// Block: 256 thr, 128(o) x 128(l) tile, K chunks of 16, 8x8 per-thread.
// tx indexes the o-fragment so outLC float4 stores are fully coalesced.
// ---------------------------------------------------------------------------
__global__ __launch_bounds__(256)
void gemm_kernel(const float* __restrict__ W, const float* __restrict__ bias,
                 const float* __restrict__ X,
                 float* __restrict__ outLC, float* __restrict__ outCL,
                 const float* __restrict__ sb, float* __restrict__ stats,
                 int L, int KD) {
    __shared__ float As[16][128];
    __shared__ float Bs[16][128];
    __shared__ float redsum[256], redsq[256];

    int tid = threadIdx.x;
    int tx = tid & 15;        // o fragment
    int ty = tid >> 4;        // l fragment
    int bb = blockIdx.y;
    int l0 = blockIdx.x * 128;
    int lrow = tid >> 1;      // 0..127 row for loads
    int cc = (tid & 1) * 8;

    float acc[8][8];
    #pragma unroll
    for (int i = 0; i < 8; i++)
        #pragma unroll
        for (int j = 0; j < 8; j++) acc[i][j] = 0.f;

    const float* Xb = X + (size_t)bb * L * KD;
    const float* sbb = sb ? (sb + (size_t)bb * C * 2) : nullptr;

    for (int c0 = 0; c0 < KD; c0 += 16) {
        #pragma unroll
        for (int i = 0; i < 2; i++) {
            float4 v = *(const float4*)&W[(size_t)lrow * KD + c0 + cc + i * 4];
            As[cc + i * 4 + 0][lrow] = v.x;
            As[cc + i * 4 + 1][lrow] = v.y;
            As[cc + i * 4 + 2][lrow] = v.z;
            As[cc + i * 4 + 3][lrow] = v.w;
        }
        #pragma unroll
        for (int i = 0; i < 2; i++) {
            float4 v = *(const float4*)&Xb[(size_t)(l0 + lrow) * KD + c0 + cc + i * 4];
            float vv[4] = {v.x, v.y, v.z, v.w};
            if (sbb) {
                #pragma unroll
                for (int q = 0; q < 4; q++) {
                    float2 t = *(const float2*)&sbb[(c0 + cc + i * 4 + q) * 2];
                    float y = vv[q] * t.x + t.y;
                    vv[q] = fmaxf(y, 0.1f * y);    // leaky relu
                }
            }
            Bs[cc + i * 4 + 0][lrow] = vv[0];
            Bs[cc + i * 4 + 1][lrow] = vv[1];
            Bs[cc + i * 4 + 2][lrow] = vv[2];
            Bs[cc + i * 4 + 3][lrow] = vv[3];
        }
        __syncthreads();
        #pragma unroll
        for (int cstep = 0; cstep < 16; cstep++) {
            float a[8], bf[8];
            *(float4*)&a[0]  = *(const float4*)&As[cstep][tx * 8];
            *(float4*)&a[4]  = *(const float4*)&As[cstep][tx * 8 + 4];
            *(float4*)&bf[0] = *(const float4*)&Bs[cstep][ty * 8];
            *(float4*)&bf[4] = *(const float4*)&Bs[cstep][ty * 8 + 4];
            #pragma unroll
            for (int i = 0; i < 8; i++)
                #pragma unroll
                for (int j = 0; j < 8; j++)
                    acc[i][j] += a[i] * bf[j];
        }
        __syncthreads();
    }

    // bias
    #pragma unroll
    for (int i = 0; i < 8; i++) {
        float bi = bias[tx * 8 + i];
        #pragma unroll
        for (int j = 0; j < 8; j++) acc[i][j] += bi;
    }

    float lsum = 0.f, lsq = 0.f;
    if (stats) {
        #pragma unroll
        for (int i = 0; i < 8; i++)
            #pragma unroll
            for (int j = 0; j < 8; j++) { lsum += acc[i][j]; lsq += acc[i][j] * acc[i][j]; }
    }
    if (outLC) {
        #pragma unroll
        for (int j = 0; j < 8; j++) {
            int l = l0 + ty * 8 + j;
            float4* p = (float4*)&outLC[((size_t)bb * L + l) * C + tx * 8];
            p[0] = make_float4(acc[0][j], acc[1][j], acc[2][j], acc[3][j]);
            p[1] = make_float4(acc[4][j], acc[5][j], acc[6][j], acc[7][j]);
        }
    }
    if (outCL) {
        #pragma unroll
        for (int i = 0; i < 8; i++) {
            float4* p = (float4*)&outCL[(size_t)bb * C * L + (size_t)(tx * 8 + i) * L + l0 + ty * 8];
            p[0] = make_float4(acc[i][0], acc[i][1], acc[i][2], acc[i][3]);
            p[1] = make_float4(acc[i][4], acc[i][5], acc[i][6], acc[i][7]);
        }
    }
    if (stats) {
        int g = tx >> 1;
        int slot = g * 32 + (tx & 1) * 16 + ty;   // bijection 0..255, group-major
        redsum[slot] = lsum; redsq[slot] = lsq;
        __syncthreads();
        #pragma unroll
        for (int off = 16; off > 0; off >>= 1) {
            if ((slot & 31) < off) {
                redsum[slot] += redsum[slot + off];
                redsq[slot]  += redsq[slot + off];
            }
            __syncthreads();
        }
        if ((slot & 31) == 0) {
            atomicAdd(&stats[(bb * GRP + g) * 2 + 0], redsum[slot]);
            atomicAdd(&stats[(bb * GRP + g) * 2 + 1], redsq[slot]);
        }
    }
}

// ---------------------------------------------------------------------------
// Maxpool over k with fused GN(scale,bias)+lrelu applied per element.
// outLC: [B][N][C] (for later conv), outCL: [B][C][N] (final output) — nullable.
// ---------------------------------------------------------------------------
__global__ void maxpool_kernel(const float* __restrict__ X,
                               const float* __restrict__ sb,
                               float* __restrict__ outLC,
                               float* __restrict__ outCL) {
    __shared__ float tile[32][129];
    int c = threadIdx.x;
    int b = blockIdx.y;
    int n0 = blockIdx.x * 32;
    float s  = sb[((size_t)b * C + c) * 2 + 0];
    float bb = sb[((size_t)b * C + c) * 2 + 1];
    for (int np = 0; np < 32; np++) {
        int n = n0 + np;
        float acc = -3.4e38f;
        #pragma unroll
        for (int k = 0; k < KNN_K; k++) {
            float v = X[(((size_t)b * NPTS + n) * KNN_K + k) * C + c];
            v = v * s + bb;
            v = fmaxf(v, 0.1f * v);
            acc = fmaxf(acc, v);
        }
        if (outLC) outLC[((size_t)b * NPTS + n) * C + c] = acc;
        tile[np][c] = acc;
    }
    __syncthreads();
    if (outCL) {
        int w = c >> 5, lane = c & 31;
        #pragma unroll
        for (int i = 0; i < 32; i++) {
            int ch = w + i * 4;
            outCL[(size_t)b * C * NPTS + (size_t)ch * NPTS + n0 + lane] = tile[lane][ch];
        }
    }
}

// ---------------------------------------------------------------------------
// Host orchestration
// ---------------------------------------------------------------------------
static inline float* fsym(const void* p) { return (float*)p; }

extern "C" void kernel_launch(void* const* d_in, const int* in_sizes, int n_in,
                              void* d_out, int out_size) {
    const float* pc1    = (const float*)d_in[0];
    const float* pc2    = (const float*)d_in[1];
    const float* feat1  = (const float*)d_in[2];
    const float* feat2  = (const float*)d_in[3];
    const float* t11_w  = (const float*)d_in[4];
    const float* t11_b  = (const float*)d_in[5];
    const float* t22_w  = (const float*)d_in[6];
    const float* t22_b  = (const float*)d_in[7];
    const float* pos1_w = (const float*)d_in[8];
    const float* pos1_b = (const float*)d_in[9];
    const float* gn1_g  = (const float*)d_in[10];
    const float* gn1_b  = (const float*)d_in[11];
    const float* m1a_w  = (const float*)d_in[12];
    const float* m1a_b  = (const float*)d_in[13];
    const float* m1a_g  = (const float*)d_in[14];
    const float* m1a_bt = (const float*)d_in[15];
    const float* m1b_w  = (const float*)d_in[16];
    const float* m1b_b  = (const float*)d_in[17];
    const float* m1b_g  = (const float*)d_in[18];
    const float* m1b_bt = (const float*)d_in[19];
    const float* t1_w   = (const float*)d_in[20];
    const float* t1_b   = (const float*)d_in[21];
    const float* t2_w   = (const float*)d_in[22];
    const float* t2_b   = (const float*)d_in[23];
    const float* pos2_w = (const float*)d_in[24];
    const float* pos2_b = (const float*)d_in[25];
    const float* gn2_g  = (const float*)d_in[26];
    const float* gn2_b  = (const float*)d_in[27];
    const float* m2a_w  = (const float*)d_in[28];
    const float* m2a_b  = (const float*)d_in[29];
    const float* m2a_g  = (const float*)d_in[30];
    const float* m2a_bt = (const float*)d_in[31];
    float* out = (float*)d_out;

    // device-global scratch addresses
    void *pA, *pB, *pF1T, *pF2T, *pf1, *pf2, *pg1, *pg2, *pf1n, *pf2n,
         *pcross, *pi12, *pi21, *pstats, *psb;
    cudaGetSymbolAddress(&pA, g_XA);
    cudaGetSymbolAddress(&pB, g_XB);
    cudaGetSymbolAddress(&pF1T, g_feat1T);
    cudaGetSymbolAddress(&pF2T, g_feat2T);
    cudaGetSymbolAddress(&pf1, g_f1T);
    cudaGetSymbolAddress(&pf2, g_f2T);
    cudaGetSymbolAddress(&pg1, g_g1T);
    cudaGetSymbolAddress(&pg2, g_g2T);
    cudaGetSymbolAddress(&pf1n, g_f1nT);
    cudaGetSymbolAddress(&pf2n, g_f2nT);
    cudaGetSymbolAddress(&pcross, g_cross);
    cudaGetSymbolAddress(&pi12, g_idx12);
    cudaGetSymbolAddress(&pi21, g_idx21);
    cudaGetSymbolAddress(&pstats, g_stats);
    cudaGetSymbolAddress(&psb, g_sb);

    float* XA = fsym(pA);  float* XB = fsym(pB);
    float* feat1T = fsym(pF1T); float* feat2T = fsym(pF2T);
    float* f1T = fsym(pf1); float* f2T = fsym(pf2);
    float* g1T = fsym(pg1); float* g2T = fsym(pg2);
    float* f1nT = fsym(pf1n); float* f2nT = fsym(pf2n);
    float* crossT = fsym(pcross);
    int* idx12 = (int*)pi12; int* idx21 = (int*)pi21;
    float* stats = fsym(pstats);
    float* sb = fsym(psb);

    const size_t BCN = (size_t)BATCH * C * NPTS;   // 1048576

    auto STAT = [&](int s) { return stats + s * BATCH * GRP * 2; };
    auto SB   = [&](int s) { return sb + s * BATCH * C * 2; };

    dim3 gridBig(LBIG / 128, BATCH);
    dim3 gridSm(NPTS / 128, BATCH);
    dim3 gridAsm(NPTS / 32, BATCH);
    dim3 gridKnn(NPTS, BATCH);

    // --- init / preprocessing ---
    zero_stats_kernel<<<1, 256>>>();
    transpose64_kernel<<<(BATCH * NPTS * CIN) / 256, 256>>>(feat1, feat1T);
    transpose64_kernel<<<(BATCH * NPTS * CIN) / 256, 256>>>(feat2, feat2T);

    // f1=t11*feat1, f2=t22*feat2, g1=t11*feat2, g2=t22*feat1   (all [B][N][C])
    gemm_kernel<<<gridSm, 256>>>(t11_w, t11_b, feat1T, f1T, nullptr, nullptr, nullptr, NPTS, CIN);
    gemm_kernel<<<gridSm, 256>>>(t22_w, t22_b, feat2T, f2T, nullptr, nullptr, nullptr, NPTS, CIN);
    gemm_kernel<<<gridSm, 256>>>(t11_w, t11_b, feat2T, g1T, nullptr, nullptr, nullptr, NPTS, CIN);
    gemm_kernel<<<gridSm, 256>>>(t22_w, t22_b, feat1T, g2T, nullptr, nullptr, nullptr, NPTS, CIN);

    knn_kernel<<<gridKnn, 256>>>(pc1, pc2, idx12);
    knn_kernel<<<gridKnn, 256>>>(pc2, pc1, idx21);

    // ---------------- cross 1: (pc1, pc2, f1, f2) pos1/gn1/mlp1 ----------------
    assemble_kernel<<<gridAsm, 128>>>(pc1, pc2, f1T, f2T, idx12, pos1_w, pos1_b, XA, STAT(0));
    finalize_kernel<<<1, 256>>>(STAT(0), gn1_g, gn1_b, SB(0), GN_INVCOUNT);
    gemm_kernel<<<gridBig, 256>>>(m1a_w, m1a_b, XA, XB, nullptr, SB(0), STAT(1), LBIG, C);
    finalize_kernel<<<1, 256>>>(STAT(1), m1a_g, m1a_bt, SB(1), GN_INVCOUNT);
    gemm_kernel<<<gridBig, 256>>>(m1b_w, m1b_b, XB, XA, nullptr, SB(1), STAT(2), LBIG, C);
    finalize_kernel<<<1, 256>>>(STAT(2), m1b_g, m1b_bt, SB(2), GN_INVCOUNT);
    maxpool_kernel<<<gridAsm, 128>>>(XA, SB(2), crossT, nullptr);
    // feat1_new = t1 * cross1  -> d_out[0] ([B][C][N]) + scratch [B][N][C]
    gemm_kernel<<<gridSm, 256>>>(t1_w, t1_b, crossT, f1nT, out, nullptr, nullptr, NPTS, C);

    // ---------------- cross 2: (pc2, pc1, g1, g2) pos1/gn1/mlp1 ----------------
    assemble_kernel<<<gridAsm, 128>>>(pc2, pc1, g1T, g2T, idx21, pos1_w, pos1_b, XA, STAT(3));
    finalize_kernel<<<1, 256>>>(STAT(3), gn1_g, gn1_b, SB(3), GN_INVCOUNT);
    gemm_kernel<<<gridBig, 256>>>(m1a_w, m1a_b, XA, XB, nullptr, SB(3), STAT(4), LBIG, C);
    finalize_kernel<<<1, 256>>>(STAT(4), m1a_g, m1a_bt, SB(4), GN_INVCOUNT);
    gemm_kernel<<<gridBig, 256>>>(m1b_w, m1b_b, XB, XA, nullptr, SB(4), STAT(5), LBIG, C);
    finalize_kernel<<<1, 256>>>(STAT(5), m1b_g, m1b_bt, SB(5), GN_INVCOUNT);
    maxpool_kernel<<<gridAsm, 128>>>(XA, SB(5), crossT, nullptr);
    // feat2_new = t2 * cross2 -> d_out[BCN] + scratch
    gemm_kernel<<<gridSm, 256>>>(t2_w, t2_b, crossT, f2nT, out + BCN, nullptr, nullptr, NPTS, C);

    // ---------------- cross 3: (pc1, pc2, feat1_new, feat2_new) pos2/gn2/mlp2 --
    assemble_kernel<<<gridAsm, 128>>>(pc1, pc2, f1nT, f2nT, idx12, pos2_w, pos2_b, XA, STAT(6));
    finalize_kernel<<<1, 256>>>(STAT(6), gn2_g, gn2_b, SB(6), GN_INVCOUNT);
    gemm_kernel<<<gridBig, 256>>>(m2a_w, m2a_b, XA, XB, nullptr, SB(6), STAT(7), LBIG, C);
    finalize_kernel<<<1, 256>>>(STAT(7), m2a_g, m2a_bt, SB(7), GN_INVCOUNT);
    // feat1_final = maxpool -> d_out[2*BCN] ([B][C][N])
    maxpool_kernel<<<gridAsm, 128>>>(XB, SB(7), nullptr, out + 2 * BCN);
}

// round 3
// speedup vs baseline: 1.5486x; 1.5486x over previous
#include <cuda_runtime.h>
#include <cuda_bf16.h>
#include <cstdint>

// ---------------------------------------------------------------------------
// Problem constants
// ---------------------------------------------------------------------------
constexpr int BATCH = 2;
constexpr int NPTS  = 4096;
constexpr int KNN_K = 16;
constexpr int C     = 128;
constexpr int CIN   = 64;
constexpr int GRP   = 8;
constexpr int LBIG  = NPTS * KNN_K;   // 65536
constexpr float GN_EPS = 1e-5f;
constexpr float GN_INVCOUNT = 1.0f / (16.0f * NPTS * KNN_K);
constexpr int PK = 40;                // smem bf16 row pitch (80B: 16B-aligned, ldmatrix conflict-free)

// ---------------------------------------------------------------------------
// Scratch (device globals; allocation-free per harness rules)
// ---------------------------------------------------------------------------
__device__ float g_feat1T[BATCH * NPTS * CIN];
__device__ float g_feat2T[BATCH * NPTS * CIN];
__device__ float g_f1T[BATCH * NPTS * C];
__device__ float g_f2T[BATCH * NPTS * C];
__device__ float g_g1T[BATCH * NPTS * C];
__device__ float g_g2T[BATCH * NPTS * C];
__device__ float g_f1nT[BATCH * NPTS * C];
__device__ float g_f2nT[BATCH * NPTS * C];
__device__ float g_cross[BATCH * NPTS * C];
__device__ int   g_idx12[BATCH * NPTS * KNN_K];
__device__ int   g_idx21[BATCH * NPTS * KNN_K];
__device__ float g_XA[(size_t)BATCH * LBIG * C];   // 64 MB
__device__ float g_XB[(size_t)BATCH * LBIG * C];   // 64 MB
__device__ float g_stats[8 * BATCH * GRP * 2];
__device__ float g_sb[8 * BATCH * C * 2];

__global__ void zero_stats_kernel() {
    int i = threadIdx.x;
    g_stats[i] = 0.0f;
}

// ---------------------------------------------------------------------------
// Transpose [B][CIN][N] -> [B][N][CIN]
// ---------------------------------------------------------------------------
__global__ void transpose64_kernel(const float* __restrict__ in, float* __restrict__ out) {
    int i = blockIdx.x * 256 + threadIdx.x;
    int c = i & 63;
    int n = (i >> 6) & (NPTS - 1);
    int b = i >> 18;
    out[i] = __ldg(&in[((size_t)b * CIN + c) * NPTS + n]);
}

// ---------------------------------------------------------------------------
// Transpose [B][N][C] -> [B][C][N]  (for t1/t2 outputs into d_out)
// ---------------------------------------------------------------------------
__global__ void lc2cl_kernel(const float* __restrict__ in, float* __restrict__ out) {
    __shared__ float t[32][33];
    int b = blockIdx.z;
    int n0 = blockIdx.x * 32, c0 = blockIdx.y * 32;
    int x = threadIdx.x, y = threadIdx.y;   // 32 x 8
    #pragma unroll
    for (int i = 0; i < 32; i += 8)
        t[y + i][x] = in[((size_t)b * NPTS + n0 + y + i) * C + c0 + x];
    __syncthreads();
    #pragma unroll
    for (int i = 0; i < 32; i += 8)
        out[(size_t)b * C * NPTS + (size_t)(c0 + y + i) * NPTS + n0 + x] = t[x][y + i];
}

// ---------------------------------------------------------------------------
// KNN: distances held in 16 registers per thread. Per round: shfl block
// argmin (2 barriers), owner thread invalidates + recomputes its local min.
// ---------------------------------------------------------------------------
__device__ __forceinline__ unsigned long long knn_key(float d, int j) {
    unsigned u = __float_as_uint(d);
    u = (u & 0x80000000u) ? ~u : (u | 0x80000000u);
    return ((unsigned long long)u << 32) | (unsigned)j;
}

__global__ void knn_kernel(const float* __restrict__ xyzQ,
                           const float* __restrict__ xyzD,
                           int* __restrict__ out) {
    __shared__ unsigned long long wred[8];
    __shared__ unsigned long long swin;
    int n = blockIdx.x, b = blockIdx.y, tid = threadIdx.x;
    const float* Q = xyzQ + (size_t)b * 3 * NPTS;
    const float* D = xyzD + (size_t)b * 3 * NPTS;
    float qx = Q[n], qy = Q[NPTS + n], qz = Q[2 * NPTS + n];
    float s1 = qx * qx + qy * qy + qz * qz;

    float myd[16];
    #pragma unroll
    for (int i = 0; i < 16; i++) {
        int j = tid + (i << 8);
        float px = D[j], py = D[NPTS + j], pz = D[2 * NPTS + j];
        float dot = qx * px + qy * py + qz * pz;
        float s2 = px * px + py * py + pz * pz;
        myd[i] = s1 + s2 - 2.0f * dot;
    }
    unsigned long long localbest = ~0ull;
    #pragma unroll
    for (int i = 0; i < 16; i++)
        localbest = min(localbest, knn_key(myd[i], tid + (i << 8)));

    for (int r = 0; r < KNN_K; r++) {
        unsigned long long best = localbest;
        #pragma unroll
        for (int off = 16; off; off >>= 1)
            best = min(best, __shfl_down_sync(0xffffffffu, best, off));
        if ((tid & 31) == 0) wred[tid >> 5] = best;
        __syncthreads();
        if (tid == 0) {
            unsigned long long m = wred[0];
            #pragma unroll
            for (int i = 1; i < 8; i++) m = min(m, wred[i]);
            swin = m;
            out[((size_t)b * NPTS + n) * KNN_K + r] = (int)(m & 0xffffffffu);
        }
        __syncthreads();
        int jwin = (int)(swin & 0xffffffffu);
        if ((jwin & 255) == tid) {
            int k = jwin >> 8;
            #pragma unroll
            for (int i = 0; i < 16; i++) if (i == k) myd[i] = __int_as_float(0x7f800000);
            localbest = ~0ull;
            #pragma unroll
            for (int i = 0; i < 16; i++)
                localbest = min(localbest, knn_key(myd[i], tid + (i << 8)));
        }
    }
}

// ---------------------------------------------------------------------------
// Assemble: X0[b][n*16+k][c] = p2T[idx] + p1T[n] + pos(dir), + group stats
// ---------------------------------------------------------------------------
__global__ void assemble_kernel(const float* __restrict__ xyz1,
                                const float* __restrict__ xyz2,
                                const float* __restrict__ p1T,
                                const float* __restrict__ p2T,
                                const int* __restrict__ idx,
                                const float* __restrict__ posw,
                                const float* __restrict__ posb,
                                float* __restrict__ X0,
                                float* __restrict__ stats) {
    __shared__ float sdx[16], sdy[16], sdz[16];
    __shared__ int sj[16];
    __shared__ float rs[128], rq[128];
    int c = threadIdx.x;
    int b = blockIdx.y;
    int nbase = blockIdx.x * 32;
    float pwx = posw[c * 3 + 0], pwy = posw[c * 3 + 1], pwz = posw[c * 3 + 2];
    float pb = posb[c];
    float lsum = 0.f, lsq = 0.f;
    const float* x1 = xyz1 + (size_t)b * 3 * NPTS;
    const float* x2 = xyz2 + (size_t)b * 3 * NPTS;
    for (int np = 0; np < 32; np++) {
        int n = nbase + np;
        __syncthreads();
        if (c < 16) {
            int j = idx[((size_t)b * NPTS + n) * KNN_K + c];
            sj[c] = j;
            sdx[c] = x2[j]            - x1[n];
            sdy[c] = x2[NPTS + j]     - x1[NPTS + n];
            sdz[c] = x2[2 * NPTS + j] - x1[2 * NPTS + n];
        }
        __syncthreads();
        float p1v = p1T[((size_t)b * NPTS + n) * C + c];
        #pragma unroll
        for (int k = 0; k < KNN_K; k++) {
            float v = p2T[((size_t)b * NPTS + sj[k]) * C + c] + p1v +
                      pwx * sdx[k] + pwy * sdy[k] + pwz * sdz[k] + pb;
            X0[(((size_t)b * NPTS + n) * KNN_K + k) * C + c] = v;
            lsum += v; lsq += v * v;
        }
    }
    rs[c] = lsum; rq[c] = lsq;
    __syncthreads();
    #pragma unroll
    for (int off = 8; off > 0; off >>= 1) {
        if ((c & 15) < off) { rs[c] += rs[c + off]; rq[c] += rq[c + off]; }
        __syncthreads();
    }
    if ((c & 15) == 0) {
        int g = c >> 4;
        atomicAdd(&stats[(b * GRP + g) * 2 + 0], rs[c]);
        atomicAdd(&stats[(b * GRP + g) * 2 + 1], rq[c]);
    }
}

// ---------------------------------------------------------------------------
// Finalize GN stats -> per-channel (scale, bias)
// ---------------------------------------------------------------------------
__global__ void finalize_kernel(const float* __restrict__ stats,
                                const float* __restrict__ gamma,
                                const float* __restrict__ beta,
                                float* __restrict__ sb,
                                float invcount) {
    int i = threadIdx.x;              // 256 = B*C
    int b = i >> 7, c = i & 127, g = c >> 4;
    float sum = stats[(b * GRP + g) * 2 + 0];
    float sq  = stats[(b * GRP + g) * 2 + 1];
    float mean = sum * invcount;
    float var  = sq * invcount - mean * mean;
    float s = gamma[c] * rsqrtf(var + GN_EPS);
    sb[i * 2 + 0] = s;
    sb[i * 2 + 1] = beta[c] - mean * s;
}

// ---------------------------------------------------------------------------
// Tensor-core GEMM (bf16 split): out[l][o] = sum_c W[o][c] * f(X[l][c]) + bias
//   f = identity or lrelu(x*scale_c+bias_c) (sb != null; fused GN)
//   stats: per-(b,group) sum/sumsq of outputs (nullable)
//   Block tile 128(o) x 128(l), K chunks of 32, 8 warps as 4(M) x 2(L).
// ---------------------------------------------------------------------------
__device__ __forceinline__ void ldm4(uint32_t r[4], const __nv_bfloat16* p) {
    uint32_t a = (uint32_t)__cvta_generic_to_shared(p);
    asm volatile("ldmatrix.sync.aligned.m8n8.x4.shared.b16 {%0,%1,%2,%3}, [%4];"
                 : "=r"(r[0]), "=r"(r[1]), "=r"(r[2]), "=r"(r[3]) : "r"(a));
}
__device__ __forceinline__ void mma16816(float c[4], const uint32_t a[4], const uint32_t* b) {
    asm volatile("mma.sync.aligned.m16n8k16.row.col.f32.bf16.bf16.f32 "
                 "{%0,%1,%2,%3}, {%4,%5,%6,%7}, {%8,%9}, {%0,%1,%2,%3};"
                 : "+f"(c[0]), "+f"(c[1]), "+f"(c[2]), "+f"(c[3])
                 : "r"(a[0]), "r"(a[1]), "r"(a[2]), "r"(a[3]), "r"(b[0]), "r"(b[1]));
}

__global__ __launch_bounds__(256)
void tgemm_kernel(const float* __restrict__ W, const float* __restrict__ bias,
                  const float* __restrict__ X, float* __restrict__ outLC,
                  const float* __restrict__ sb, float* __restrict__ stats,
                  int L, int KD) {
    __shared__ __align__(16) unsigned char smem_raw[128 * PK * 2 * 4];  // 40960 B
    __shared__ float sgrp[GRP][2];

    __nv_bfloat16* wh = (__nv_bfloat16*)smem_raw;
    __nv_bfloat16* wl = wh + 128 * PK;
    __nv_bfloat16* xh = wl + 128 * PK;
    __nv_bfloat16* xl = xh + 128 * PK;
    float* stage = (float*)smem_raw;        // reused in epilogue (33792 B)

    int tid = threadIdx.x;
    int lane = tid & 31, w = tid >> 5;
    int bb = blockIdx.y;
    int l0 = blockIdx.x * 128;
    int warpM = (w >> 1) * 32;
    int warpL = (w & 1) * 64;

    const float* Xb = X + (size_t)bb * L * KD;
    const float* sbb = sb ? sb + bb * C * 2 : nullptr;

    if (tid < 2 * GRP) ((float*)sgrp)[tid] = 0.f;

    float acc[2][8][4];
    #pragma unroll
    for (int mt = 0; mt < 2; mt++)
        #pragma unroll
        for (int nt = 0; nt < 8; nt++)
            #pragma unroll
            for (int q = 0; q < 4; q++) acc[mt][nt][q] = 0.f;

    int lrow = tid >> 1;
    int colq = (tid & 1) * 16;

    // ldmatrix per-lane row/col offsets
    int rA = (lane & 7) + ((lane >> 3) & 1) * 8;
    int cA = ((lane >> 4) & 1) * 8;
    int rB = (lane & 7) + ((lane >> 4) & 1) * 8;
    int cB = ((lane >> 3) & 1) * 8;

    for (int c0 = 0; c0 < KD; c0 += 32) {
        // ---- load W tile (fp32 -> bf16 hi/lo) ----
        {
            const float* wsrc = W + (size_t)lrow * KD + c0 + colq;
            #pragma unroll
            for (int j = 0; j < 4; j++) {
                float4 v = *(const float4*)(wsrc + j * 4);
                float vv[4] = {v.x, v.y, v.z, v.w};
                __nv_bfloat16 hh[4], ll[4];
                #pragma unroll
                for (int q = 0; q < 4; q++) {
                    hh[q] = __float2bfloat16(vv[q]);
                    ll[q] = __float2bfloat16(vv[q] - __bfloat162float(hh[q]));
                }
                int off = lrow * PK + colq + j * 4;
                *(__nv_bfloat162*)(wh + off)     = __halves2bfloat162(hh[0], hh[1]);
                *(__nv_bfloat162*)(wh + off + 2) = __halves2bfloat162(hh[2], hh[3]);
                *(__nv_bfloat162*)(wl + off)     = __halves2bfloat162(ll[0], ll[1]);
                *(__nv_bfloat162*)(wl + off + 2) = __halves2bfloat162(ll[2], ll[3]);
            }
        }
        // ---- load X tile (fp32 -> GN+lrelu -> bf16 hi/lo) ----
        {
            const float* xsrc = Xb + (size_t)(l0 + lrow) * KD + c0 + colq;
            #pragma unroll
            for (int j = 0; j < 4; j++) {
                float4 v = *(const float4*)(xsrc + j * 4);
                float vv[4] = {v.x, v.y, v.z, v.w};
                if (sbb) {
                    #pragma unroll
                    for (int q = 0; q < 4; q++) {
                        float2 t = *(const float2*)&sbb[(c0 + colq + j * 4 + q) * 2];
                        float y = vv[q] * t.x + t.y;
                        vv[q] = fmaxf(y, 0.1f * y);
                    }
                }
                __nv_bfloat16 hh[4], ll[4];
                #pragma unroll
                for (int q = 0; q < 4; q++) {
                    hh[q] = __float2bfloat16(vv[q]);
                    ll[q] = __float2bfloat16(vv[q] - __bfloat162float(hh[q]));
                }
                int off = lrow * PK + colq + j * 4;
                *(__nv_bfloat162*)(xh + off)     = __halves2bfloat162(hh[0], hh[1]);
                *(__nv_bfloat162*)(xh + off + 2) = __halves2bfloat162(hh[2], hh[3]);
                *(__nv_bfloat162*)(xl + off)     = __halves2bfloat162(ll[0], ll[1]);
                *(__nv_bfloat162*)(xl + off + 2) = __halves2bfloat162(ll[2], ll[3]);
            }
        }
        __syncthreads();

        #pragma unroll
        for (int s = 0; s < 2; s++) {
            uint32_t ah[2][4], al[2][4];
            #pragma unroll
            for (int mt = 0; mt < 2; mt++) {
                ldm4(ah[mt], wh + (warpM + mt * 16 + rA) * PK + s * 16 + cA);
                ldm4(al[mt], wl + (warpM + mt * 16 + rA) * PK + s * 16 + cA);
            }
            #pragma unroll
            for (int np = 0; np < 4; np++) {
                uint32_t bh[4], bl[4];
                ldm4(bh, xh + (warpL + np * 16 + rB) * PK + s * 16 + cB);
                ldm4(bl, xl + (warpL + np * 16 + rB) * PK + s * 16 + cB);
                #pragma unroll
                for (int mt = 0; mt < 2; mt++) {
                    #pragma unroll
                    for (int sub = 0; sub < 2; sub++) {
                        int nt = np * 2 + sub;
                        mma16816(acc[mt][nt], ah[mt], &bh[sub * 2]);
                        mma16816(acc[mt][nt], ah[mt], &bl[sub * 2]);
                        mma16816(acc[mt][nt], al[mt], &bh[sub * 2]);
                    }
                }
            }
        }
        __syncthreads();
    }

    // ---- epilogue: bias, stats ----
    #pragma unroll
    for (int mt = 0; mt < 2; mt++) {
        float b0 = __ldg(&bias[warpM + mt * 16 + (lane >> 2)]);
        float b1 = __ldg(&bias[warpM + mt * 16 + (lane >> 2) + 8]);
        float lsum = 0.f, lsq = 0.f;
        #pragma unroll
        for (int nt = 0; nt < 8; nt++) {
            acc[mt][nt][0] += b0; acc[mt][nt][1] += b0;
            acc[mt][nt][2] += b1; acc[mt][nt][3] += b1;
            if (stats) {
                #pragma unroll
                for (int q = 0; q < 4; q++) {
                    float v = acc[mt][nt][q];
                    lsum += v; lsq += v * v;
                }
            }
        }
        if (stats) {
            #pragma unroll
            for (int off = 16; off; off >>= 1) {
                lsum += __shfl_down_sync(0xffffffffu, lsum, off);
                lsq  += __shfl_down_sync(0xffffffffu, lsq, off);
            }
            if (lane == 0) {
                int g = (warpM + mt * 16) >> 4;
                atomicAdd(&sgrp[g][0], lsum);
                atomicAdd(&sgrp[g][1], lsq);
            }
        }
    }

    // ---- store via smem stage (two L-halves), coalesced float4 ----
    #pragma unroll
    for (int p = 0; p < 2; p++) {
        __syncthreads();
        if ((w & 1) == p) {
            #pragma unroll
            for (int mt = 0; mt < 2; mt++) {
                int oc = warpM + mt * 16 + (lane >> 2);
                #pragma unroll
                for (int nt = 0; nt < 8; nt++) {
                    int lc = nt * 8 + (lane & 3) * 2;
                    stage[(lc + 0) * 132 + oc]     = acc[mt][nt][0];
                    stage[(lc + 1) * 132 + oc]     = acc[mt][nt][1];
                    stage[(lc + 0) * 132 + oc + 8] = acc[mt][nt][2];
                    stage[(lc + 1) * 132 + oc + 8] = acc[mt][nt][3];
                }
            }
        }
        __syncthreads();
        int lr = tid >> 2;
        int q0 = (tid & 3) * 8;
        float* dst = outLC + ((size_t)bb * L + l0 + p * 64 + lr) * C;
        #pragma unroll
        for (int i = 0; i < 8; i++)
            *(float4*)(dst + (q0 + i) * 4) = *(const float4*)(stage + lr * 132 + (q0 + i) * 4);
    }

    if (stats && tid < GRP) {
        atomicAdd(&stats[(bb * GRP + tid) * 2 + 0], sgrp[tid][0]);
        atomicAdd(&stats[(bb * GRP + tid) * 2 + 1], sgrp[tid][1]);
    }
}

// ---------------------------------------------------------------------------
// Maxpool over k with fused GN + lrelu; outLC and/or outCL
// ---------------------------------------------------------------------------
__global__ void maxpool_kernel(const float* __restrict__ X,
                               const float* __restrict__ sb,
                               float* __restrict__ outLC,
                               float* __restrict__ outCL) {
    __shared__ float tile[32][129];
    int c = threadIdx.x;
    int b = blockIdx.y;
    int n0 = blockIdx.x * 32;
    float s  = sb[((size_t)b * C + c) * 2 + 0];
    float bb = sb[((size_t)b * C + c) * 2 + 1];
    for (int np = 0; np < 32; np++) {
        int n = n0 + np;
        float acc = -3.4e38f;
        #pragma unroll
        for (int k = 0; k < KNN_K; k++) {
            float v = X[(((size_t)b * NPTS + n) * KNN_K + k) * C + c];
            v = v * s + bb;
            v = fmaxf(v, 0.1f * v);
            acc = fmaxf(acc, v);
        }
        if (outLC) outLC[((size_t)b * NPTS + n) * C + c] = acc;
        tile[np][c] = acc;
    }
    __syncthreads();
    if (outCL) {
        int w = c >> 5, lane = c & 31;
        #pragma unroll
        for (int i = 0; i < 32; i++) {
            int ch = w + i * 4;
            outCL[(size_t)b * C * NPTS + (size_t)ch * NPTS + n0 + lane] = tile[lane][ch];
        }
    }
}

// ---------------------------------------------------------------------------
// Host orchestration
// ---------------------------------------------------------------------------
static inline float* fsym(const void* p) { return (float*)p; }

extern "C" void kernel_launch(void* const* d_in, const int* in_sizes, int n_in,
                              void* d_out, int out_size) {
    const float* pc1    = (const float*)d_in[0];
    const float* pc2    = (const float*)d_in[1];
    const float* feat1  = (const float*)d_in[2];
    const float* feat2  = (const float*)d_in[3];
    const float* t11_w  = (const float*)d_in[4];
    const float* t11_b  = (const float*)d_in[5];
    const float* t22_w  = (const float*)d_in[6];
    const float* t22_b  = (const float*)d_in[7];
    const float* pos1_w = (const float*)d_in[8];
    const float* pos1_b = (const float*)d_in[9];
    const float* gn1_g  = (const float*)d_in[10];
    const float* gn1_b  = (const float*)d_in[11];
    const float* m1a_w  = (const float*)d_in[12];
    const float* m1a_b  = (const float*)d_in[13];
    const float* m1a_g  = (const float*)d_in[14];
    const float* m1a_bt = (const float*)d_in[15];
    const float* m1b_w  = (const float*)d_in[16];
    const float* m1b_b  = (const float*)d_in[17];
    const float* m1b_g  = (const float*)d_in[18];
    const float* m1b_bt = (const float*)d_in[19];
    const float* t1_w   = (const float*)d_in[20];
    const float* t1_b   = (const float*)d_in[21];
    const float* t2_w   = (const float*)d_in[22];
    const float* t2_b   = (const float*)d_in[23];
    const float* pos2_w = (const float*)d_in[24];
    const float* pos2_b = (const float*)d_in[25];
    const float* gn2_g  = (const float*)d_in[26];
    const float* gn2_b  = (const float*)d_in[27];
    const float* m2a_w  = (const float*)d_in[28];
    const float* m2a_b  = (const float*)d_in[29];
    const float* m2a_g  = (const float*)d_in[30];
    const float* m2a_bt = (const float*)d_in[31];
    float* out = (float*)d_out;

    void *pA, *pB, *pF1T, *pF2T, *pf1, *pf2, *pg1, *pg2, *pf1n, *pf2n,
         *pcross, *pi12, *pi21, *pstats, *psb;
    cudaGetSymbolAddress(&pA, g_XA);
    cudaGetSymbolAddress(&pB, g_XB);
    cudaGetSymbolAddress(&pF1T, g_feat1T);
    cudaGetSymbolAddress(&pF2T, g_feat2T);
    cudaGetSymbolAddress(&pf1, g_f1T);
    cudaGetSymbolAddress(&pf2, g_f2T);
    cudaGetSymbolAddress(&pg1, g_g1T);
    cudaGetSymbolAddress(&pg2, g_g2T);
    cudaGetSymbolAddress(&pf1n, g_f1nT);
    cudaGetSymbolAddress(&pf2n, g_f2nT);
    cudaGetSymbolAddress(&pcross, g_cross);
    cudaGetSymbolAddress(&pi12, g_idx12);
    cudaGetSymbolAddress(&pi21, g_idx21);
    cudaGetSymbolAddress(&pstats, g_stats);
    cudaGetSymbolAddress(&psb, g_sb);

    float* XA = fsym(pA);  float* XB = fsym(pB);
    float* feat1T = fsym(pF1T); float* feat2T = fsym(pF2T);
    float* f1T = fsym(pf1); float* f2T = fsym(pf2);
    float* g1T = fsym(pg1); float* g2T = fsym(pg2);
    float* f1nT = fsym(pf1n); float* f2nT = fsym(pf2n);
    float* crossT = fsym(pcross);
    int* idx12 = (int*)pi12; int* idx21 = (int*)pi21;
    float* stats = fsym(pstats);
    float* sb = fsym(psb);

    const size_t BCN = (size_t)BATCH * C * NPTS;

    auto STAT = [&](int s) { return stats + s * BATCH * GRP * 2; };
    auto SB   = [&](int s) { return sb + s * BATCH * C * 2; };

    dim3 gridBig(LBIG / 128, BATCH);
    dim3 gridSm(NPTS / 128, BATCH);
    dim3 gridAsm(NPTS / 32, BATCH);
    dim3 gridKnn(NPTS, BATCH);
    dim3 gridT(NPTS / 32, C / 32, BATCH);
    dim3 blkT(32, 8);

    zero_stats_kernel<<<1, 256>>>();
    transpose64_kernel<<<(BATCH * NPTS * CIN) / 256, 256>>>(feat1, feat1T);
    transpose64_kernel<<<(BATCH * NPTS * CIN) / 256, 256>>>(feat2, feat2T);

    tgemm_kernel<<<gridSm, 256>>>(t11_w, t11_b, feat1T, f1T, nullptr, nullptr, NPTS, CIN);
    tgemm_kernel<<<gridSm, 256>>>(t22_w, t22_b, feat2T, f2T, nullptr, nullptr, NPTS, CIN);
    tgemm_kernel<<<gridSm, 256>>>(t11_w, t11_b, feat2T, g1T, nullptr, nullptr, NPTS, CIN);
    tgemm_kernel<<<gridSm, 256>>>(t22_w, t22_b, feat1T, g2T, nullptr, nullptr, NPTS, CIN);

    knn_kernel<<<gridKnn, 256>>>(pc1, pc2, idx12);
    knn_kernel<<<gridKnn, 256>>>(pc2, pc1, idx21);

    // ---------------- cross 1 ----------------
    assemble_kernel<<<gridAsm, 128>>>(pc1, pc2, f1T, f2T, idx12, pos1_w, pos1_b, XA, STAT(0));
    finalize_kernel<<<1, 256>>>(STAT(0), gn1_g, gn1_b, SB(0), GN_INVCOUNT);
    tgemm_kernel<<<gridBig, 256>>>(m1a_w, m1a_b, XA, XB, SB(0), STAT(1), LBIG, C);
    finalize_kernel<<<1, 256>>>(STAT(1), m1a_g, m1a_bt, SB(1), GN_INVCOUNT);
    tgemm_kernel<<<gridBig, 256>>>(m1b_w, m1b_b, XB, XA, SB(1), STAT(2), LBIG, C);
    finalize_kernel<<<1, 256>>>(STAT(2), m1b_g, m1b_bt, SB(2), GN_INVCOUNT);
    maxpool_kernel<<<gridAsm, 128>>>(XA, SB(2), crossT, nullptr);
    tgemm_kernel<<<gridSm, 256>>>(t1_w, t1_b, crossT, f1nT, nullptr, nullptr, NPTS, C);
    lc2cl_kernel<<<gridT, blkT>>>(f1nT, out);

    // ---------------- cross 2 ----------------
    assemble_kernel<<<gridAsm, 128>>>(pc2, pc1, g1T, g2T, idx21, pos1_w, pos1_b, XA, STAT(3));
    finalize_kernel<<<1, 256>>>(STAT(3), gn1_g, gn1_b, SB(3), GN_INVCOUNT);
    tgemm_kernel<<<gridBig, 256>>>(m1a_w, m1a_b, XA, XB, SB(3), STAT(4), LBIG, C);
    finalize_kernel<<<1, 256>>>(STAT(4), m1a_g, m1a_bt, SB(4), GN_INVCOUNT);
    tgemm_kernel<<<gridBig, 256>>>(m1b_w, m1b_b, XB, XA, SB(4), STAT(5), LBIG, C);
    finalize_kernel<<<1, 256>>>(STAT(5), m1b_g, m1b_bt, SB(5), GN_INVCOUNT);
    maxpool_kernel<<<gridAsm, 128>>>(XA, SB(5), crossT, nullptr);
    tgemm_kernel<<<gridSm, 256>>>(t2_w, t2_b, crossT, f2nT, nullptr, nullptr, NPTS, C);
    lc2cl_kernel<<<gridT, blkT>>>(f2nT, out + BCN);

    // ---------------- cross 3 ----------------
    assemble_kernel<<<gridAsm, 128>>>(pc1, pc2, f1nT, f2nT, idx12, pos2_w, pos2_b, XA, STAT(6));
    finalize_kernel<<<1, 256>>>(STAT(6), gn2_g, gn2_b, SB(6), GN_INVCOUNT);
    tgemm_kernel<<<gridBig, 256>>>(m2a_w, m2a_b, XA, XB, SB(6), STAT(7), LBIG, C);
    finalize_kernel<<<1, 256>>>(STAT(7), m2a_g, m2a_bt, SB(7), GN_INVCOUNT);
    maxpool_kernel<<<gridAsm, 128>>>(XB, SB(7), nullptr, out + 2 * BCN);
}